// round 13
// baseline (speedup 1.0000x reference)
#include <cuda_runtime.h>
#include <cstdint>

// Problem constants (fixed shapes from setup_inputs)
#define LSEQ 2048
#define HDIM 1024
#define EDIM 1024
#define GB 128          // persistent blocks (1 per SM, all co-resident)
#define TB 256          // threads per persistent block
#define HPB 8           // h elements owned per block (128*8 = 1024)

// ---------------- scratch (static device globals; no dynamic alloc) ----------------
__device__ float g_target[EDIM];
__device__ float g_zc[2][4 * HDIM];   // w_ih@target + b_ih + b_hh per direction
__device__ float g_zf[2][4 * HDIM];   // w_ih@seq[first] + b_ih + b_hh per direction
__device__ int   g_meta[4];           // {fl_step, fl_tok, fr_step, fr_tok}
// tagged ping-pong h: each element is ((tag)<<32) | float_bits(h).
// Accessed ONLY with strong relaxed 8B atomics -> defined under race, no tearing.
__device__ __align__(16) unsigned long long g_hx[2][HDIM];
__device__ __align__(16) float g_hsl [(size_t)LSEQ * HDIM];  // left-pass hiddens (8 MB)
__device__ __align__(16) float g_prod[(size_t)LSEQ * HDIM];  // hs_l * hs_r       (8 MB)
__device__ float g_beta[LSEQ];
__device__ float g_alfa[LSEQ];
__device__ float g_s[HDIM];

// ---------------- math helpers ----------------
__device__ __forceinline__ float sigf(float x)     { return 1.0f / (1.0f + __expf(-x)); }
__device__ __forceinline__ float tanhfast(float x) { return 1.0f - 2.0f / (1.0f + __expf(2.0f * x)); }
// packed f32x2 FMA (Blackwell): d = a*b + c elementwise on 2 packed floats
__device__ __forceinline__ unsigned long long ffma2(unsigned long long a,
                                                    unsigned long long b,
                                                    unsigned long long c) {
    unsigned long long d;
    asm("fma.rn.f32x2 %0, %1, %2, %3;" : "=l"(d) : "l"(a), "l"(b), "l"(c));
    return d;
}
__device__ __forceinline__ float2 unpack2(unsigned long long v) {
    float2 f;
    asm("mov.b64 {%0, %1}, %2;" : "=f"(f.x), "=f"(f.y) : "l"(v));
    return f;
}
// strong relaxed 8B atomics: atomic value, no fence, no load-load ordering (pipelined)
__device__ __forceinline__ unsigned long long ld_rlx64(const unsigned long long* p) {
    unsigned long long v;
    asm volatile("ld.relaxed.gpu.global.u64 %0, [%1];" : "=l"(v) : "l"(p) : "memory");
    return v;
}
__device__ __forceinline__ void st_rlx64(unsigned long long* p, unsigned long long v) {
    asm volatile("st.relaxed.gpu.global.u64 [%0], %1;" :: "l"(p), "l"(v) : "memory");
}

// ---------------- kernel A: target mean, meta scalars, init tagged h ----------------
__global__ void prep_kernel(const int* __restrict__ x, const int* __restrict__ ts,
                            const int* __restrict__ te, const float* __restrict__ emb) {
    int start = ts[0], end = te[0];
    int tid = blockIdx.x * blockDim.x + threadIdx.x;   // 0..1023
    float s = 0.0f;
    for (int t = start; t <= end; t++)
        s += emb[(size_t)x[t] * EDIM + tid];
    g_target[tid] = s / (float)(end - start + 1);
    g_beta[tid] = 0.0f;
    g_beta[1024 + tid] = 0.0f;
    g_s[tid] = 0.0f;
    // reset BOTH slots every launch (graph replays would otherwise alias stale tags)
    g_hx[0][tid] = 0ull;    // h(0) = 0.0, tag 0
    g_hx[1][tid] = 0ull;
    if (tid == 0) {
        int fl = (start > 0) ? 0 : (end + 1);
        g_meta[0] = (fl < LSEQ) ? fl : -1;
        g_meta[1] = (fl < LSEQ) ? fl : 0;
        int frs, frt;
        if (end < LSEQ - 1)      { frs = 0;            frt = LSEQ - 1;  }
        else if (start > 0)      { frs = LSEQ - start; frt = start - 1; }
        else                     { frs = -1;           frt = 0;         }
        g_meta[2] = frs; g_meta[3] = frt;
    }
}

// ---------------- kernel B: z vectors (4 matvecs 4096x1024), one block per output row ----
__global__ void zvec_kernel(const int* __restrict__ x, const float* __restrict__ emb,
                            const float* __restrict__ wil, const float* __restrict__ bil,
                            const float* __restrict__ bhl,
                            const float* __restrict__ wir, const float* __restrict__ bir,
                            const float* __restrict__ bhr) {
    int bid = blockIdx.x;
    int dir = bid >> 12;           // 0: left, 1: right
    int row = bid & 4095;
    const float* wi = dir ? wir : wil;
    const float* bi = dir ? bir : bil;
    const float* bh = dir ? bhr : bhl;
    int tokpos = dir ? g_meta[3] : g_meta[1];
    int tok = x[tokpos];
    const float* wrow = wi + (size_t)row * EDIM;
    const float* trow = emb + (size_t)tok * EDIM;
    int tid = threadIdx.x;
    float sc = 0.0f, sf = 0.0f;
    for (int e = tid; e < EDIM; e += 128) {
        float wv = wrow[e];
        sc += wv * g_target[e];
        sf += wv * trow[e];
    }
    #pragma unroll
    for (int off = 16; off; off >>= 1) {
        sc += __shfl_xor_sync(0xffffffffu, sc, off);
        sf += __shfl_xor_sync(0xffffffffu, sf, off);
    }
    __shared__ float r1[4], r2[4];
    int wid = tid >> 5, lane = tid & 31;
    if (lane == 0) { r1[wid] = sc; r2[wid] = sf; }
    __syncthreads();
    if (tid == 0) {
        float bb = bi[row] + bh[row];
        g_zc[dir][row] = r1[0] + r1[1] + r1[2] + r1[3] + bb;
        g_zf[dir][row] = r2[0] + r2[1] + r2[2] + r2[3] + bb;
    }
}

// ---------------- kernel C: persistent LSTM recurrence (both directions) ----------------
// 128 blocks x 256 threads, all resident. Weights in registers as packed f32x2 pairs.
// Sync = tagged dataflow with STRONG RELAXED 8B atomics: tag and h travel in ONE word,
// so readiness and data arrive in the same load. No fences, no counters, no RED.
// WAR safety: ping-pong slots + causality (a block can publish tag s+2 into a slot only
// after every block finished reading that slot's tag-s values — acyclic rf/hb chain).
__global__ void __launch_bounds__(TB, 1)
lstm_kernel(const float* __restrict__ whl, const float* __restrict__ whr) {
    __shared__ float rs[32];
    __shared__ __align__(16) float sm_h[HDIM];

    const int tid  = threadIdx.x;
    const int lane = tid & 31;
    const int w    = tid >> 5;
    const int hbase = blockIdx.x * HPB;

    // warp-0 per-lane gate roles: lane t -> gate q = t>>3, element k = t&7
    const int q = lane >> 3, k = lane & 7;
    const bool is_g = (q == 2);
    float c_reg = 0.0f;                 // lanes 0..7 carry c (persists across directions)

    ulonglong2 wv[4][8];
    for (int dir = 0; dir < 2; dir++) {
        const float* W = dir ? whr : whl;
        // load this thread's 128 weights into registers (as packed f32x2 pairs)
        #pragma unroll
        for (int r = 0; r < 4; r++) {
            int lr = 4 * w + r;
            int qq = lr >> 3, kk = lr & 7;
            const ulonglong2* wrow =
                (const ulonglong2*)(W + (size_t)(qq * HDIM + hbase + kk) * HDIM);
            #pragma unroll
            for (int j = 0; j < 8; j++) wv[r][j] = wrow[j * 32 + lane];
        }
        float zc_r = 0.0f, zf_r = 0.0f;
        if (w == 0) {
            zc_r = g_zc[dir][q * HDIM + hbase + k];
            zf_r = g_zf[dir][q * HDIM + hbase + k];
        }
        const int special = dir ? g_meta[2] : g_meta[0];
        __syncthreads();

        for (int step = 0; step < LSEQ; step++) {
            const unsigned s = (unsigned)(dir * LSEQ + step);
            const size_t rowoff = (size_t)step * HDIM + hbase;

            // prefetch own left-pass h for the prod store (same thread wrote it in dir 0)
            float hsl_pref = 0.0f;
            if (dir == 1 && w == 0 && lane < HPB)
                hsl_pref = __ldcg(&g_hsl[rowoff + lane]);

            // ---- staging warps 6,7: poll tagged h (relaxed strong) into SMEM ----
            // 64 lanes x one 128B line each -> 128 pollers/line chip-wide (proven safe)
            if (w >= 6) {
                const int sl = tid - 192;              // 0..63
                unsigned long long* base = g_hx[s & 1u] + (size_t)sl * 16;
                unsigned long long a[16];
                for (;;) {
                    unsigned mn = 0xffffffffu;
                    #pragma unroll
                    for (int i = 0; i < 16; i++) {
                        a[i] = ld_rlx64(base + i);     // pipelined: no ordering between
                        unsigned tg = (unsigned)(a[i] >> 32);
                        mn = (tg < mn) ? tg : mn;
                    }
                    if (mn >= s) break;                // tag==s exactly (or stale s-2)
                }
                float2* dst = (float2*)sm_h + sl * 8;  // 16 floats per lane
                #pragma unroll
                for (int i = 0; i < 8; i++)
                    dst[i] = make_float2(__uint_as_float((unsigned)a[2 * i]),
                                         __uint_as_float((unsigned)a[2 * i + 1]));
            }
            __syncthreads();   // bar 1: sm_h(s) ready

            // ---- 4 gate-rows per warp: packed-FMA dot products over SMEM h ----
            const ulonglong2* hp = (const ulonglong2*)sm_h;
            ulonglong2 hv[8];
            #pragma unroll
            for (int j = 0; j < 8; j++) hv[j] = hp[j * 32 + lane];

            #pragma unroll
            for (int r = 0; r < 4; r++) {
                unsigned long long a0 = 0ull, a1 = 0ull;
                #pragma unroll
                for (int j = 0; j < 8; j++) {
                    a0 = ffma2(wv[r][j].x, hv[j].x, a0);
                    a1 = ffma2(wv[r][j].y, hv[j].y, a1);
                }
                float2 p = unpack2(a0), q2 = unpack2(a1);
                float a = (p.x + p.y) + (q2.x + q2.y);
                #pragma unroll
                for (int off = 16; off; off >>= 1)
                    a += __shfl_xor_sync(0xffffffffu, a, off);
                if (lane == 0) rs[4 * w + r] = a;
            }
            __syncthreads();   // bar 2: rs ready (also orders sm_h reads before next write)

            // ---- warp 0: gates (exact __expf path), publish tagged h ----
            if (w == 0) {
                float pre = rs[lane] + ((step == special) ? zf_r : zc_r);
                // single-exp per lane: tanh(x) = 2*sigmoid(2x) - 1
                float xin = is_g ? (2.0f * pre) : pre;
                float sg = sigf(xin);
                float act = is_g ? (2.0f * sg - 1.0f) : sg;
                float gi = __shfl_sync(0xffffffffu, act, k);
                float gf = __shfl_sync(0xffffffffu, act, k + 8);
                float gg = __shfl_sync(0xffffffffu, act, k + 16);
                float go = __shfl_sync(0xffffffffu, act, k + 24);
                if (lane < HPB) {
                    float c = gf * c_reg + gi * gg;
                    c_reg = c;
                    float h = go * tanhfast(c);
                    unsigned long long pair =
                        ((unsigned long long)(s + 1u) << 32) |
                        (unsigned long long)__float_as_uint(h);
                    st_rlx64(&g_hx[(s + 1u) & 1u][hbase + lane], pair);  // atomic word
                    // non-critical stores after the publish
                    if (dir == 0) g_hsl[rowoff + lane] = h;
                    else          g_prod[rowoff + lane] = h * hsl_pref;
                }
            }
            // no bar 3: staging warps self-synchronize on tags; sm_h/rs WAR ordered by
            // bar 2 and the tag-chain induction (writers of step s+1 state can't run
            // until every block's readers of step s finished).
        }
        __syncthreads();
    }
}

// ---------------- kernel D: beta[t] = sum_j u[j]*tanh(lin1_w[j,:]·prod[t,:] + b[j]) ------
__global__ void beta_kernel(const float* __restrict__ l1w, const float* __restrict__ l1b,
                            const float* __restrict__ u) {
    __shared__ float sA[32][33];
    __shared__ __align__(16) float sBT[32][128];
    __shared__ float red[8][32];

    const int tid = threadIdx.x;
    const int t0 = blockIdx.x * 32;
    const int j0 = blockIdx.y * 128;
    const int t  = tid & 31;
    const int jg = tid >> 5;

    float acc[16];
    #pragma unroll
    for (int m = 0; m < 16; m++) acc[m] = 0.0f;

    const float4* prod4 = (const float4*)g_prod;

    for (int kc = 0; kc < HDIM; kc += 32) {
        {
            int tl = tid >> 3;
            int k0 = (tid & 7) * 4;
            float4 v = prod4[(size_t)(t0 + tl) * 256 + (kc >> 2) + (tid & 7)];
            sA[tl][k0 + 0] = v.x; sA[tl][k0 + 1] = v.y;
            sA[tl][k0 + 2] = v.z; sA[tl][k0 + 3] = v.w;
        }
        {
            int jj = tid >> 1;
            int koff = (tid & 1) * 16;
            const float4* wr = (const float4*)(l1w + (size_t)(j0 + jj) * HDIM + kc + koff);
            #pragma unroll
            for (int q4 = 0; q4 < 4; q4++) {
                float4 v = wr[q4];
                sBT[koff + q4 * 4 + 0][jj] = v.x;
                sBT[koff + q4 * 4 + 1][jj] = v.y;
                sBT[koff + q4 * 4 + 2][jj] = v.z;
                sBT[koff + q4 * 4 + 3][jj] = v.w;
            }
        }
        __syncthreads();
        #pragma unroll 8
        for (int kk = 0; kk < 32; kk++) {
            float a = sA[t][kk];
            const float4* brow = (const float4*)(&sBT[kk][jg * 16]);
            float4 b0 = brow[0], b1 = brow[1], b2 = brow[2], b3 = brow[3];
            acc[0]  += a * b0.x; acc[1]  += a * b0.y; acc[2]  += a * b0.z; acc[3]  += a * b0.w;
            acc[4]  += a * b1.x; acc[5]  += a * b1.y; acc[6]  += a * b1.z; acc[7]  += a * b1.w;
            acc[8]  += a * b2.x; acc[9]  += a * b2.y; acc[10] += a * b2.z; acc[11] += a * b2.w;
            acc[12] += a * b3.x; acc[13] += a * b3.y; acc[14] += a * b3.z; acc[15] += a * b3.w;
        }
        __syncthreads();
    }

    float partial = 0.0f;
    #pragma unroll
    for (int m = 0; m < 16; m++) {
        int j = j0 + jg * 16 + m;
        float val = acc[m] + l1b[j];
        partial += tanhfast(val) * u[j];
    }
    red[jg][t] = partial;
    __syncthreads();
    if (tid < 32) {
        float s = 0.0f;
        #pragma unroll
        for (int g2 = 0; g2 < 8; g2++) s += red[g2][tid];
        atomicAdd(&g_beta[t0 + tid], s);
    }
}

// ---------------- kernel E: softmax over beta[2048] -> alfa ----------------
__global__ void softmax_kernel() {
    __shared__ float sm[256];
    int tid = threadIdx.x;
    float v[8];
    float mx = -1e30f;
    #pragma unroll
    for (int i = 0; i < 8; i++) { v[i] = g_beta[tid * 8 + i]; mx = fmaxf(mx, v[i]); }
    sm[tid] = mx; __syncthreads();
    for (int s = 128; s; s >>= 1) { if (tid < s) sm[tid] = fmaxf(sm[tid], sm[tid + s]); __syncthreads(); }
    mx = sm[0]; __syncthreads();
    float sum = 0.0f;
    #pragma unroll
    for (int i = 0; i < 8; i++) { v[i] = __expf(v[i] - mx); sum += v[i]; }
    sm[tid] = sum; __syncthreads();
    for (int s = 128; s; s >>= 1) { if (tid < s) sm[tid] += sm[tid + s]; __syncthreads(); }
    float inv = 1.0f / sm[0];
    #pragma unroll
    for (int i = 0; i < 8; i++) g_alfa[tid * 8 + i] = v[i] * inv;
}

// ---------------- kernel F: s[j] = sum_t alfa[t] * prod[t,j] ----------------
__global__ void sred_kernel() {
    int tid = threadIdx.x;
    int t0 = blockIdx.x * 64;
    float4 acc = make_float4(0.f, 0.f, 0.f, 0.f);
    const float4* p4 = (const float4*)g_prod;
    for (int t = 0; t < 64; t++) {
        float a = g_alfa[t0 + t];
        float4 p = p4[(size_t)(t0 + t) * 256 + tid];
        acc.x += a * p.x; acc.y += a * p.y; acc.z += a * p.z; acc.w += a * p.w;
    }
    atomicAdd(&g_s[tid * 4 + 0], acc.x);
    atomicAdd(&g_s[tid * 4 + 1], acc.y);
    atomicAdd(&g_s[tid * 4 + 2], acc.z);
    atomicAdd(&g_s[tid * 4 + 3], acc.w);
}

// ---------------- kernel G: out[p] = s · lin2_w[p,:] + lin2_b[p], p=0..2 ----------------
__global__ void final_kernel(const float* __restrict__ l2w, const float* __restrict__ l2b,
                             float* __restrict__ out) {
    int wp = threadIdx.x >> 5, lane = threadIdx.x & 31;
    if (wp < 3) {
        float s = 0.0f;
        for (int j = lane; j < HDIM; j += 32)
            s += g_s[j] * l2w[wp * HDIM + j];
        #pragma unroll
        for (int off = 16; off; off >>= 1) s += __shfl_xor_sync(0xffffffffu, s, off);
        if (lane == 0) out[wp] = s + l2b[wp];
    }
}

// ---------------- launch ----------------
extern "C" void kernel_launch(void* const* d_in, const int* in_sizes, int n_in,
                              void* d_out, int out_size) {
    (void)in_sizes; (void)n_in; (void)out_size;
    const int*   x   = (const int*)d_in[0];
    const int*   ts  = (const int*)d_in[1];
    const int*   te  = (const int*)d_in[2];
    const float* emb = (const float*)d_in[3];
    const float* wil = (const float*)d_in[4];
    const float* whl = (const float*)d_in[5];
    const float* bil = (const float*)d_in[6];
    const float* bhl = (const float*)d_in[7];
    const float* wir = (const float*)d_in[8];
    const float* whr = (const float*)d_in[9];
    const float* bir = (const float*)d_in[10];
    const float* bhr = (const float*)d_in[11];
    const float* l1w = (const float*)d_in[12];
    const float* l1b = (const float*)d_in[13];
    const float* u   = (const float*)d_in[14];
    const float* l2w = (const float*)d_in[15];
    const float* l2b = (const float*)d_in[16];
    float* out = (float*)d_out;

    prep_kernel<<<8, 128>>>(x, ts, te, emb);
    zvec_kernel<<<8192, 128>>>(x, emb, wil, bil, bhl, wir, bir, bhr);
    lstm_kernel<<<GB, TB>>>(whl, whr);
    beta_kernel<<<dim3(LSEQ / 32, HDIM / 128), 256>>>(l1w, l1b, u);
    softmax_kernel<<<1, 256>>>();
    sred_kernel<<<32, 256>>>();
    final_kernel<<<1, 128>>>(l2w, l2b, out);
}

// round 15
// speedup vs baseline: 2.5460x; 2.5460x over previous
#include <cuda_runtime.h>
#include <cstdint>

// Problem constants (fixed shapes from setup_inputs)
#define LSEQ 2048
#define HDIM 1024
#define EDIM 1024
#define GB 128          // persistent blocks (1 per SM, all co-resident)
#define TB 256          // threads per persistent block
#define HPB 8           // h elements owned per block (128*8 = 1024)

// ---------------- scratch (static device globals; no dynamic alloc) ----------------
__device__ float g_target[EDIM];
__device__ float g_zc[2][4 * HDIM];   // w_ih@target + b_ih + b_hh per direction
__device__ float g_zf[2][4 * HDIM];   // w_ih@seq[first] + b_ih + b_hh per direction
__device__ int   g_meta[4];           // {fl_step, fl_tok, fr_step, fr_tok}
__device__ __align__(16) float g_hbuf[2][HDIM];              // ping-pong h
__device__ __align__(16) float g_hsl [(size_t)LSEQ * HDIM];  // left-pass hiddens (8 MB)
__device__ __align__(16) float g_prod[(size_t)LSEQ * HDIM];  // hs_l * hs_r       (8 MB)
__device__ float g_beta[LSEQ];
__device__ float g_alfa[LSEQ];
__device__ float g_s[HDIM];
__device__ unsigned g_ctrs[4 * 32];   // 4 barrier counters, 128B apart (different L2 lines)

// ---------------- math helpers ----------------
__device__ __forceinline__ float sigf(float x)     { return 1.0f / (1.0f + __expf(-x)); }
__device__ __forceinline__ float tanhfast(float x) { return 1.0f - 2.0f / (1.0f + __expf(2.0f * x)); }
__device__ __forceinline__ unsigned ld_acq(const unsigned* p) {
    unsigned v;
    asm volatile("ld.acquire.gpu.u32 %0, [%1];" : "=r"(v) : "l"(p) : "memory");
    return v;
}
__device__ __forceinline__ void red_release_add(unsigned* p, unsigned v) {
    asm volatile("red.release.gpu.global.add.u32 [%0], %1;" :: "l"(p), "r"(v) : "memory");
}
// packed f32x2 FMA (Blackwell): d = a*b + c elementwise on 2 packed floats
__device__ __forceinline__ unsigned long long ffma2(unsigned long long a,
                                                    unsigned long long b,
                                                    unsigned long long c) {
    unsigned long long d;
    asm("fma.rn.f32x2 %0, %1, %2, %3;" : "=l"(d) : "l"(a), "l"(b), "l"(c));
    return d;
}
__device__ __forceinline__ float2 unpack2(unsigned long long v) {
    float2 f;
    asm("mov.b64 {%0, %1}, %2;" : "=f"(f.x), "=f"(f.y) : "l"(v));
    return f;
}

// ---------------- kernel A: target mean, meta scalars, init state ----------------
__global__ void prep_kernel(const int* __restrict__ x, const int* __restrict__ ts,
                            const int* __restrict__ te, const float* __restrict__ emb) {
    int start = ts[0], end = te[0];
    int tid = blockIdx.x * blockDim.x + threadIdx.x;   // 0..1023
    float s = 0.0f;
    for (int t = start; t <= end; t++)
        s += emb[(size_t)x[t] * EDIM + tid];
    g_target[tid] = s / (float)(end - start + 1);
    g_beta[tid] = 0.0f;
    g_beta[1024 + tid] = 0.0f;
    g_s[tid] = 0.0f;
    g_hbuf[0][tid] = 0.0f;          // step-0 input h = 0
    if (tid < 4 * 32) g_ctrs[tid] = 0;   // reset barrier counters every launch (graph replays)
    if (tid == 0) {
        int fl = (start > 0) ? 0 : (end + 1);
        g_meta[0] = (fl < LSEQ) ? fl : -1;
        g_meta[1] = (fl < LSEQ) ? fl : 0;
        int frs, frt;
        if (end < LSEQ - 1)      { frs = 0;            frt = LSEQ - 1;  }
        else if (start > 0)      { frs = LSEQ - start; frt = start - 1; }
        else                     { frs = -1;           frt = 0;         }
        g_meta[2] = frs; g_meta[3] = frt;
    }
}

// ---------------- kernel B: z vectors (4 matvecs 4096x1024), one block per output row ----
__global__ void zvec_kernel(const int* __restrict__ x, const float* __restrict__ emb,
                            const float* __restrict__ wil, const float* __restrict__ bil,
                            const float* __restrict__ bhl,
                            const float* __restrict__ wir, const float* __restrict__ bir,
                            const float* __restrict__ bhr) {
    int bid = blockIdx.x;
    int dir = bid >> 12;           // 0: left, 1: right
    int row = bid & 4095;
    const float* wi = dir ? wir : wil;
    const float* bi = dir ? bir : bil;
    const float* bh = dir ? bhr : bhl;
    int tokpos = dir ? g_meta[3] : g_meta[1];
    int tok = x[tokpos];
    const float* wrow = wi + (size_t)row * EDIM;
    const float* trow = emb + (size_t)tok * EDIM;
    int tid = threadIdx.x;
    float sc = 0.0f, sf = 0.0f;
    for (int e = tid; e < EDIM; e += 128) {
        float wv = wrow[e];
        sc += wv * g_target[e];
        sf += wv * trow[e];
    }
    #pragma unroll
    for (int off = 16; off; off >>= 1) {
        sc += __shfl_xor_sync(0xffffffffu, sc, off);
        sf += __shfl_xor_sync(0xffffffffu, sf, off);
    }
    __shared__ float r1[4], r2[4];
    int wid = tid >> 5, lane = tid & 31;
    if (lane == 0) { r1[wid] = sc; r2[wid] = sf; }
    __syncthreads();
    if (tid == 0) {
        float bb = bi[row] + bh[row];
        g_zc[dir][row] = r1[0] + r1[1] + r1[2] + r1[3] + bb;
        g_zf[dir][row] = r2[0] + r2[1] + r2[2] + r2[3] + bb;
    }
}

// ---------------- kernel C: persistent LSTM recurrence (both directions) ----------------
// 128 blocks x 256 threads, all resident. Sync = the PROVEN R7 central barrier
// (stage->bar->compute->bar->publish+fence+RED->poll->bar). New vs R7: warp k owns
// h-element k ENTIRELY (rows k,8+k,16+k,24+k) -> after its butterfly every lane holds
// all 4 gate sums, gates computed inline in-warp (lane-distributed single-exp), h
// published by lane 0 of each warp in parallel. No rs exchange, no serial gate tail.
__global__ void __launch_bounds__(TB, 1)
lstm_kernel(const float* __restrict__ whl, const float* __restrict__ whr) {
    __shared__ __align__(16) float sm_h[HDIM];

    const int tid  = threadIdx.x;
    const int lane = tid & 31;
    const int w    = tid >> 5;          // warp = owned h element (0..7)
    const int hbase = blockIdx.x * HPB;

    float c_reg = 0.0f;                 // replicated across all lanes of warp w

    ulonglong2 wv[4][8];
    for (int dir = 0; dir < 2; dir++) {
        const float* W = dir ? whr : whl;
        // warp w loads rows {r*1024 + hbase + w}, r=0..3 into registers (f32x2 pairs)
        #pragma unroll
        for (int r = 0; r < 4; r++) {
            const ulonglong2* wrow =
                (const ulonglong2*)(W + (size_t)(r * HDIM + hbase + w) * HDIM);
            #pragma unroll
            for (int j = 0; j < 8; j++) wv[r][j] = wrow[j * 32 + lane];
        }
        // z values for this warp's 4 rows (uniform per warp, registers)
        float zc_r[4], zf_r[4];
        #pragma unroll
        for (int r = 0; r < 4; r++) {
            zc_r[r] = g_zc[dir][r * HDIM + hbase + w];
            zf_r[r] = g_zf[dir][r * HDIM + hbase + w];
        }
        const int special = dir ? g_meta[2] : g_meta[0];
        __syncthreads();

        for (int step = 0; step < LSEQ; step++) {
            const unsigned g = (unsigned)(dir * LSEQ + step);
            const size_t rowoff = (size_t)step * HDIM + hbase;

            // stage h(g) into SMEM: one 4 KB cooperative L2 read per block
            {
                float4 v = __ldcg(&((const float4*)g_hbuf[g & 1u])[tid]);
                ((float4*)sm_h)[tid] = v;
            }
            // prefetch own left-pass h for the prod store (off critical path)
            float hsl_pref = 0.0f;
            if (dir == 1 && lane == 0)
                hsl_pref = __ldcg(&g_hsl[rowoff + w]);
            __syncthreads();   // bar 1: sm_h(g) ready

            // ---- warp w: 4 gate-row dots over SMEM h (packed FMA) ----
            const ulonglong2* hp = (const ulonglong2*)sm_h;
            ulonglong2 hv[8];
            #pragma unroll
            for (int j = 0; j < 8; j++) hv[j] = hp[j * 32 + lane];

            float a0, a1, a2, a3;
            {
                unsigned long long s00 = 0ull, s01 = 0ull, s10 = 0ull, s11 = 0ull;
                unsigned long long s20 = 0ull, s21 = 0ull, s30 = 0ull, s31 = 0ull;
                #pragma unroll
                for (int j = 0; j < 8; j++) {
                    s00 = ffma2(wv[0][j].x, hv[j].x, s00);
                    s01 = ffma2(wv[0][j].y, hv[j].y, s01);
                    s10 = ffma2(wv[1][j].x, hv[j].x, s10);
                    s11 = ffma2(wv[1][j].y, hv[j].y, s11);
                    s20 = ffma2(wv[2][j].x, hv[j].x, s20);
                    s21 = ffma2(wv[2][j].y, hv[j].y, s21);
                    s30 = ffma2(wv[3][j].x, hv[j].x, s30);
                    s31 = ffma2(wv[3][j].y, hv[j].y, s31);
                }
                float2 p, q;
                p = unpack2(s00); q = unpack2(s01); a0 = (p.x + p.y) + (q.x + q.y);
                p = unpack2(s10); q = unpack2(s11); a1 = (p.x + p.y) + (q.x + q.y);
                p = unpack2(s20); q = unpack2(s21); a2 = (p.x + p.y) + (q.x + q.y);
                p = unpack2(s30); q = unpack2(s31); a3 = (p.x + p.y) + (q.x + q.y);
            }
            #pragma unroll
            for (int off = 16; off; off >>= 1) {
                a0 += __shfl_xor_sync(0xffffffffu, a0, off);
                a1 += __shfl_xor_sync(0xffffffffu, a1, off);
                a2 += __shfl_xor_sync(0xffffffffu, a2, off);
                a3 += __shfl_xor_sync(0xffffffffu, a3, off);
            }

            // ---- inline gates (lane-distributed single-exp, exact __expf path) ----
            const bool sp = (step == special);
            float p0 = a0 + (sp ? zf_r[0] : zc_r[0]);
            float p1 = a1 + (sp ? zf_r[1] : zc_r[1]);
            float p2 = a2 + (sp ? zf_r[2] : zc_r[2]);
            float p3 = a3 + (sp ? zf_r[3] : zc_r[3]);
            // lanes 0..3 each evaluate one activation: tanh(x) = 2*sigmoid(2x) - 1
            float pre = (lane == 0) ? p0 : (lane == 1) ? p1 : (lane == 2) ? p2 : p3;
            bool  isg = (lane == 2);
            float xin = isg ? (2.0f * pre) : pre;
            float sg  = sigf(xin);
            float act = isg ? (2.0f * sg - 1.0f) : sg;
            float gi = __shfl_sync(0xffffffffu, act, 0);
            float gf = __shfl_sync(0xffffffffu, act, 1);
            float gg = __shfl_sync(0xffffffffu, act, 2);
            float go = __shfl_sync(0xffffffffu, act, 3);
            float c = gf * c_reg + gi * gg;
            c_reg = c;
            float h = go * tanhfast(c);
            if (lane == 0) {
                __stcg(&g_hbuf[(g + 1u) & 1u][hbase + w], h);
                if (dir == 0) g_hsl[rowoff + w] = h;
                else          g_prod[rowoff + w] = h * hsl_pref;
            }
            __syncthreads();   // bar 2: all 8 h stores issued

            // ---- central barrier (R7-proven): fence + RED arrive, 4-counter poll ----
            if (tid == 0) {
                __threadfence();   // order h stores (whole block) before the arrive
                red_release_add(&g_ctrs[(blockIdx.x & 3) * 32], 1u);
            }
            if (w == 0 && lane < 4) {
                const unsigned tgt = 32u * (g + 1u);
                while (ld_acq(&g_ctrs[lane * 32]) < tgt) {}
            }
            __syncthreads();   // bar 3: h(g+1) globally visible
        }
    }
}

// ---------------- kernel D: beta[t] = sum_j u[j]*tanh(lin1_w[j,:]·prod[t,:] + b[j]) ------
__global__ void beta_kernel(const float* __restrict__ l1w, const float* __restrict__ l1b,
                            const float* __restrict__ u) {
    __shared__ float sA[32][33];
    __shared__ __align__(16) float sBT[32][128];
    __shared__ float red[8][32];

    const int tid = threadIdx.x;
    const int t0 = blockIdx.x * 32;
    const int j0 = blockIdx.y * 128;
    const int t  = tid & 31;
    const int jg = tid >> 5;

    float acc[16];
    #pragma unroll
    for (int m = 0; m < 16; m++) acc[m] = 0.0f;

    const float4* prod4 = (const float4*)g_prod;

    for (int kc = 0; kc < HDIM; kc += 32) {
        {
            int tl = tid >> 3;
            int k0 = (tid & 7) * 4;
            float4 v = prod4[(size_t)(t0 + tl) * 256 + (kc >> 2) + (tid & 7)];
            sA[tl][k0 + 0] = v.x; sA[tl][k0 + 1] = v.y;
            sA[tl][k0 + 2] = v.z; sA[tl][k0 + 3] = v.w;
        }
        {
            int jj = tid >> 1;
            int koff = (tid & 1) * 16;
            const float4* wr = (const float4*)(l1w + (size_t)(j0 + jj) * HDIM + kc + koff);
            #pragma unroll
            for (int q4 = 0; q4 < 4; q4++) {
                float4 v = wr[q4];
                sBT[koff + q4 * 4 + 0][jj] = v.x;
                sBT[koff + q4 * 4 + 1][jj] = v.y;
                sBT[koff + q4 * 4 + 2][jj] = v.z;
                sBT[koff + q4 * 4 + 3][jj] = v.w;
            }
        }
        __syncthreads();
        #pragma unroll 8
        for (int kk = 0; kk < 32; kk++) {
            float a = sA[t][kk];
            const float4* brow = (const float4*)(&sBT[kk][jg * 16]);
            float4 b0 = brow[0], b1 = brow[1], b2 = brow[2], b3 = brow[3];
            acc[0]  += a * b0.x; acc[1]  += a * b0.y; acc[2]  += a * b0.z; acc[3]  += a * b0.w;
            acc[4]  += a * b1.x; acc[5]  += a * b1.y; acc[6]  += a * b1.z; acc[7]  += a * b1.w;
            acc[8]  += a * b2.x; acc[9]  += a * b2.y; acc[10] += a * b2.z; acc[11] += a * b2.w;
            acc[12] += a * b3.x; acc[13] += a * b3.y; acc[14] += a * b3.z; acc[15] += a * b3.w;
        }
        __syncthreads();
    }

    float partial = 0.0f;
    #pragma unroll
    for (int m = 0; m < 16; m++) {
        int j = j0 + jg * 16 + m;
        float val = acc[m] + l1b[j];
        partial += tanhfast(val) * u[j];
    }
    red[jg][t] = partial;
    __syncthreads();
    if (tid < 32) {
        float s = 0.0f;
        #pragma unroll
        for (int g2 = 0; g2 < 8; g2++) s += red[g2][tid];
        atomicAdd(&g_beta[t0 + tid], s);
    }
}

// ---------------- kernel E: softmax over beta[2048] -> alfa ----------------
__global__ void softmax_kernel() {
    __shared__ float sm[256];
    int tid = threadIdx.x;
    float v[8];
    float mx = -1e30f;
    #pragma unroll
    for (int i = 0; i < 8; i++) { v[i] = g_beta[tid * 8 + i]; mx = fmaxf(mx, v[i]); }
    sm[tid] = mx; __syncthreads();
    for (int s = 128; s; s >>= 1) { if (tid < s) sm[tid] = fmaxf(sm[tid], sm[tid + s]); __syncthreads(); }
    mx = sm[0]; __syncthreads();
    float sum = 0.0f;
    #pragma unroll
    for (int i = 0; i < 8; i++) { v[i] = __expf(v[i] - mx); sum += v[i]; }
    sm[tid] = sum; __syncthreads();
    for (int s = 128; s; s >>= 1) { if (tid < s) sm[tid] += sm[tid + s]; __syncthreads(); }
    float inv = 1.0f / sm[0];
    #pragma unroll
    for (int i = 0; i < 8; i++) g_alfa[tid * 8 + i] = v[i] * inv;
}

// ---------------- kernel F: s[j] = sum_t alfa[t] * prod[t,j] ----------------
__global__ void sred_kernel() {
    int tid = threadIdx.x;
    int t0 = blockIdx.x * 64;
    float4 acc = make_float4(0.f, 0.f, 0.f, 0.f);
    const float4* p4 = (const float4*)g_prod;
    for (int t = 0; t < 64; t++) {
        float a = g_alfa[t0 + t];
        float4 p = p4[(size_t)(t0 + t) * 256 + tid];
        acc.x += a * p.x; acc.y += a * p.y; acc.z += a * p.z; acc.w += a * p.w;
    }
    atomicAdd(&g_s[tid * 4 + 0], acc.x);
    atomicAdd(&g_s[tid * 4 + 1], acc.y);
    atomicAdd(&g_s[tid * 4 + 2], acc.z);
    atomicAdd(&g_s[tid * 4 + 3], acc.w);
}

// ---------------- kernel G: out[p] = s · lin2_w[p,:] + lin2_b[p], p=0..2 ----------------
__global__ void final_kernel(const float* __restrict__ l2w, const float* __restrict__ l2b,
                             float* __restrict__ out) {
    int wp = threadIdx.x >> 5, lane = threadIdx.x & 31;
    if (wp < 3) {
        float s = 0.0f;
        for (int j = lane; j < HDIM; j += 32)
            s += g_s[j] * l2w[wp * HDIM + j];
        #pragma unroll
        for (int off = 16; off; off >>= 1) s += __shfl_xor_sync(0xffffffffu, s, off);
        if (lane == 0) out[wp] = s + l2b[wp];
    }
}

// ---------------- launch ----------------
extern "C" void kernel_launch(void* const* d_in, const int* in_sizes, int n_in,
                              void* d_out, int out_size) {
    (void)in_sizes; (void)n_in; (void)out_size;
    const int*   x   = (const int*)d_in[0];
    const int*   ts  = (const int*)d_in[1];
    const int*   te  = (const int*)d_in[2];
    const float* emb = (const float*)d_in[3];
    const float* wil = (const float*)d_in[4];
    const float* whl = (const float*)d_in[5];
    const float* bil = (const float*)d_in[6];
    const float* bhl = (const float*)d_in[7];
    const float* wir = (const float*)d_in[8];
    const float* whr = (const float*)d_in[9];
    const float* bir = (const float*)d_in[10];
    const float* bhr = (const float*)d_in[11];
    const float* l1w = (const float*)d_in[12];
    const float* l1b = (const float*)d_in[13];
    const float* u   = (const float*)d_in[14];
    const float* l2w = (const float*)d_in[15];
    const float* l2b = (const float*)d_in[16];
    float* out = (float*)d_out;

    prep_kernel<<<8, 128>>>(x, ts, te, emb);
    zvec_kernel<<<8192, 128>>>(x, emb, wil, bil, bhl, wir, bir, bhr);
    lstm_kernel<<<GB, TB>>>(whl, whr);
    beta_kernel<<<dim3(LSEQ / 32, HDIM / 128), 256>>>(l1w, l1b, u);
    softmax_kernel<<<1, 256>>>();
    sred_kernel<<<32, 256>>>();
    final_kernel<<<1, 128>>>(l2w, l2b, out);
}

// round 16
// speedup vs baseline: 2.6236x; 1.0305x over previous
#include <cuda_runtime.h>
#include <cstdint>

// Problem constants (fixed shapes from setup_inputs)
#define LSEQ 2048
#define HDIM 1024
#define EDIM 1024
#define GB 128          // persistent blocks (1 per SM, all co-resident)
#define TB 256          // threads per persistent block
#define HPB 8           // h elements owned per block (128*8 = 1024)

// ---------------- scratch (static device globals; no dynamic alloc) ----------------
__device__ float g_target[EDIM];
__device__ float g_zc[2][4 * HDIM];   // w_ih@target + b_ih + b_hh per direction
__device__ float g_zf[2][4 * HDIM];   // w_ih@seq[first] + b_ih + b_hh per direction
__device__ int   g_meta[4];           // {fl_step, fl_tok, fr_step, fr_tok}
// versioned h: row g = h before step g (row g+1 = output of step g). Each row is
// written EXACTLY ONCE per launch -> readers may use plain L1-cacheable loads
// (L1D is flushed per launch; no address reuse inside a launch).
__device__ __align__(16) float g_hall[(size_t)(2 * LSEQ + 1) * HDIM];   // 16.8 MB
__device__ __align__(16) float g_prod[(size_t)LSEQ * HDIM];  // hs_l * hs_r (8 MB)
__device__ float g_beta[LSEQ];
__device__ float g_alfa[LSEQ];
__device__ float g_s[HDIM];
__device__ unsigned g_ctrs[4 * 32];   // 4 barrier counters, 128B apart (different L2 lines)

// ---------------- math helpers ----------------
__device__ __forceinline__ float sigf(float x)     { return 1.0f / (1.0f + __expf(-x)); }
__device__ __forceinline__ float tanhfast(float x) { return 1.0f - 2.0f / (1.0f + __expf(2.0f * x)); }
__device__ __forceinline__ unsigned ld_acq(const unsigned* p) {
    unsigned v;
    asm volatile("ld.acquire.gpu.u32 %0, [%1];" : "=r"(v) : "l"(p) : "memory");
    return v;
}
__device__ __forceinline__ void red_release_add(unsigned* p, unsigned v) {
    asm volatile("red.release.gpu.global.add.u32 [%0], %1;" :: "l"(p), "r"(v) : "memory");
}
// packed f32x2 FMA (Blackwell): d = a*b + c elementwise on 2 packed floats
__device__ __forceinline__ unsigned long long ffma2(unsigned long long a,
                                                    unsigned long long b,
                                                    unsigned long long c) {
    unsigned long long d;
    asm("fma.rn.f32x2 %0, %1, %2, %3;" : "=l"(d) : "l"(a), "l"(b), "l"(c));
    return d;
}
__device__ __forceinline__ float2 unpack2(unsigned long long v) {
    float2 f;
    asm("mov.b64 {%0, %1}, %2;" : "=f"(f.x), "=f"(f.y) : "l"(v));
    return f;
}

// ---------------- kernel A: target mean, meta scalars, init state ----------------
__global__ void prep_kernel(const int* __restrict__ x, const int* __restrict__ ts,
                            const int* __restrict__ te, const float* __restrict__ emb) {
    int start = ts[0], end = te[0];
    int tid = blockIdx.x * blockDim.x + threadIdx.x;   // 0..1023
    float s = 0.0f;
    for (int t = start; t <= end; t++)
        s += emb[(size_t)x[t] * EDIM + tid];
    g_target[tid] = s / (float)(end - start + 1);
    g_beta[tid] = 0.0f;
    g_beta[1024 + tid] = 0.0f;
    g_s[tid] = 0.0f;
    g_hall[tid] = 0.0f;             // row 0: h(0) = 0
    if (tid < 4 * 32) g_ctrs[tid] = 0;   // reset barrier counters every launch (graph replays)
    if (tid == 0) {
        int fl = (start > 0) ? 0 : (end + 1);
        g_meta[0] = (fl < LSEQ) ? fl : -1;
        g_meta[1] = (fl < LSEQ) ? fl : 0;
        int frs, frt;
        if (end < LSEQ - 1)      { frs = 0;            frt = LSEQ - 1;  }
        else if (start > 0)      { frs = LSEQ - start; frt = start - 1; }
        else                     { frs = -1;           frt = 0;         }
        g_meta[2] = frs; g_meta[3] = frt;
    }
}

// ---------------- kernel B: z vectors (4 matvecs 4096x1024), one block per output row ----
__global__ void zvec_kernel(const int* __restrict__ x, const float* __restrict__ emb,
                            const float* __restrict__ wil, const float* __restrict__ bil,
                            const float* __restrict__ bhl,
                            const float* __restrict__ wir, const float* __restrict__ bir,
                            const float* __restrict__ bhr) {
    int bid = blockIdx.x;
    int dir = bid >> 12;           // 0: left, 1: right
    int row = bid & 4095;
    const float* wi = dir ? wir : wil;
    const float* bi = dir ? bir : bil;
    const float* bh = dir ? bhr : bhl;
    int tokpos = dir ? g_meta[3] : g_meta[1];
    int tok = x[tokpos];
    const float* wrow = wi + (size_t)row * EDIM;
    const float* trow = emb + (size_t)tok * EDIM;
    int tid = threadIdx.x;
    float sc = 0.0f, sf = 0.0f;
    for (int e = tid; e < EDIM; e += 128) {
        float wv = wrow[e];
        sc += wv * g_target[e];
        sf += wv * trow[e];
    }
    #pragma unroll
    for (int off = 16; off; off >>= 1) {
        sc += __shfl_xor_sync(0xffffffffu, sc, off);
        sf += __shfl_xor_sync(0xffffffffu, sf, off);
    }
    __shared__ float r1[4], r2[4];
    int wid = tid >> 5, lane = tid & 31;
    if (lane == 0) { r1[wid] = sc; r2[wid] = sf; }
    __syncthreads();
    if (tid == 0) {
        float bb = bi[row] + bh[row];
        g_zc[dir][row] = r1[0] + r1[1] + r1[2] + r1[3] + bb;
        g_zf[dir][row] = r2[0] + r2[1] + r2[2] + r2[3] + bb;
    }
}

// ---------------- kernel C: persistent LSTM recurrence (both directions) ----------------
// 128 blocks x 256 threads, all resident. Weights in registers as packed f32x2 pairs.
// Sync = R7-proven central barrier (stcg publish + fence + RED.release / acquire-poll),
// but h lives in write-once versioned rows (g_hall): readers use PLAIN L1 loads right
// after the poll+bar — no SMEM staging, no extra bar, 2 bars per step total.
__global__ void __launch_bounds__(TB, 1)
lstm_kernel(const float* __restrict__ whl, const float* __restrict__ whr) {
    __shared__ float rs[32];

    const int tid  = threadIdx.x;
    const int lane = tid & 31;
    const int w    = tid >> 5;
    const int hbase = blockIdx.x * HPB;

    // warp-0 per-lane gate roles: lane t -> gate q = t>>3, element k = t&7
    const int q = lane >> 3, k = lane & 7;
    const bool is_g = (q == 2);
    float c_reg = 0.0f;                 // lanes 0..7 carry c (persists across directions)

    ulonglong2 wv[4][8];
    for (int dir = 0; dir < 2; dir++) {
        const float* W = dir ? whr : whl;
        // load this thread's 128 weights into registers (as packed f32x2 pairs)
        #pragma unroll
        for (int r = 0; r < 4; r++) {
            int lr = 4 * w + r;
            int qq = lr >> 3, kk = lr & 7;
            const ulonglong2* wrow =
                (const ulonglong2*)(W + (size_t)(qq * HDIM + hbase + kk) * HDIM);
            #pragma unroll
            for (int j = 0; j < 8; j++) wv[r][j] = wrow[j * 32 + lane];
        }
        float zc_r = 0.0f, zf_r = 0.0f;
        if (w == 0) {
            zc_r = g_zc[dir][q * HDIM + hbase + k];
            zf_r = g_zf[dir][q * HDIM + hbase + k];
        }
        const int special = dir ? g_meta[2] : g_meta[0];
        __syncthreads();

        for (int step = 0; step < LSEQ; step++) {
            const unsigned g = (unsigned)(dir * LSEQ + step);
            const size_t rowoff = (size_t)step * HDIM + hbase;

            // ---- poll: h(g) globally published? (g=0 target is 0 -> no wait) ----
            if (w == 0 && lane < 4) {
                const unsigned tgt = g << 5;           // 32 * g
                while (ld_acq(&g_ctrs[lane * 32]) < tgt) {}
            }
            __syncthreads();   // bar A: h(g) visible; also orders rs WAR across steps

            // prefetch left-pass h for the prod store (dir 1; row step+1 is settled)
            float hsl_pref = 0.0f;
            if (dir == 1 && w == 0 && lane < HPB)
                hsl_pref = g_hall[(size_t)(step + 1) * HDIM + hbase + lane];

            // ---- plain L1 loads of h(g) (write-once row; no staleness possible) ----
            const ulonglong2* hp = (const ulonglong2*)(g_hall + (size_t)g * HDIM);
            ulonglong2 hv[8];
            #pragma unroll
            for (int j = 0; j < 8; j++) hv[j] = hp[j * 32 + lane];

            #pragma unroll
            for (int r = 0; r < 4; r++) {
                unsigned long long a0 = 0ull, a1 = 0ull;
                #pragma unroll
                for (int j = 0; j < 8; j++) {
                    a0 = ffma2(wv[r][j].x, hv[j].x, a0);
                    a1 = ffma2(wv[r][j].y, hv[j].y, a1);
                }
                float2 p = unpack2(a0), q2 = unpack2(a1);
                float a = (p.x + p.y) + (q2.x + q2.y);
                #pragma unroll
                for (int off = 16; off; off >>= 1)
                    a += __shfl_xor_sync(0xffffffffu, a, off);
                if (lane == 0) rs[4 * w + r] = a;
            }
            __syncthreads();   // bar B: rs ready

            // ---- warp 0: gates (exact __expf path), publish h(g+1), arrive ----
            if (w == 0) {
                float pre = rs[lane] + ((step == special) ? zf_r : zc_r);
                // single-exp per lane: tanh(x) = 2*sigmoid(2x) - 1
                float xin = is_g ? (2.0f * pre) : pre;
                float sg = sigf(xin);
                float act = is_g ? (2.0f * sg - 1.0f) : sg;
                float gi = __shfl_sync(0xffffffffu, act, k);
                float gf = __shfl_sync(0xffffffffu, act, k + 8);
                float gg = __shfl_sync(0xffffffffu, act, k + 16);
                float go = __shfl_sync(0xffffffffu, act, k + 24);
                float h = 0.0f;
                if (lane < HPB) {
                    float c = gf * c_reg + gi * gg;
                    c_reg = c;
                    h = go * tanhfast(c);
                    __stcg(&g_hall[(size_t)(g + 1u) * HDIM + hbase + lane], h);
                }
                __syncwarp();
                if (lane == 0) {
                    __threadfence();   // order h stores before the arrive
                    red_release_add(&g_ctrs[(blockIdx.x & 3) * 32], 1u);
                }
                // non-critical store after the arrive
                if (dir == 1 && lane < HPB)
                    g_prod[rowoff + lane] = h * hsl_pref;
            }
            // no bar here: next iteration's poll (w0) + bar A provide the ordering
        }
        __syncthreads();
    }
}

// ---------------- kernel D: beta[t] = sum_j u[j]*tanh(lin1_w[j,:]·prod[t,:] + b[j]) ------
__global__ void beta_kernel(const float* __restrict__ l1w, const float* __restrict__ l1b,
                            const float* __restrict__ u) {
    __shared__ float sA[32][33];
    __shared__ __align__(16) float sBT[32][128];
    __shared__ float red[8][32];

    const int tid = threadIdx.x;
    const int t0 = blockIdx.x * 32;
    const int j0 = blockIdx.y * 128;
    const int t  = tid & 31;
    const int jg = tid >> 5;

    float acc[16];
    #pragma unroll
    for (int m = 0; m < 16; m++) acc[m] = 0.0f;

    const float4* prod4 = (const float4*)g_prod;

    for (int kc = 0; kc < HDIM; kc += 32) {
        {
            int tl = tid >> 3;
            int k0 = (tid & 7) * 4;
            float4 v = prod4[(size_t)(t0 + tl) * 256 + (kc >> 2) + (tid & 7)];
            sA[tl][k0 + 0] = v.x; sA[tl][k0 + 1] = v.y;
            sA[tl][k0 + 2] = v.z; sA[tl][k0 + 3] = v.w;
        }
        {
            int jj = tid >> 1;
            int koff = (tid & 1) * 16;
            const float4* wr = (const float4*)(l1w + (size_t)(j0 + jj) * HDIM + kc + koff);
            #pragma unroll
            for (int q4 = 0; q4 < 4; q4++) {
                float4 v = wr[q4];
                sBT[koff + q4 * 4 + 0][jj] = v.x;
                sBT[koff + q4 * 4 + 1][jj] = v.y;
                sBT[koff + q4 * 4 + 2][jj] = v.z;
                sBT[koff + q4 * 4 + 3][jj] = v.w;
            }
        }
        __syncthreads();
        #pragma unroll 8
        for (int kk = 0; kk < 32; kk++) {
            float a = sA[t][kk];
            const float4* brow = (const float4*)(&sBT[kk][jg * 16]);
            float4 b0 = brow[0], b1 = brow[1], b2 = brow[2], b3 = brow[3];
            acc[0]  += a * b0.x; acc[1]  += a * b0.y; acc[2]  += a * b0.z; acc[3]  += a * b0.w;
            acc[4]  += a * b1.x; acc[5]  += a * b1.y; acc[6]  += a * b1.z; acc[7]  += a * b1.w;
            acc[8]  += a * b2.x; acc[9]  += a * b2.y; acc[10] += a * b2.z; acc[11] += a * b2.w;
            acc[12] += a * b3.x; acc[13] += a * b3.y; acc[14] += a * b3.z; acc[15] += a * b3.w;
        }
        __syncthreads();
    }

    float partial = 0.0f;
    #pragma unroll
    for (int m = 0; m < 16; m++) {
        int j = j0 + jg * 16 + m;
        float val = acc[m] + l1b[j];
        partial += tanhfast(val) * u[j];
    }
    red[jg][t] = partial;
    __syncthreads();
    if (tid < 32) {
        float s = 0.0f;
        #pragma unroll
        for (int g2 = 0; g2 < 8; g2++) s += red[g2][tid];
        atomicAdd(&g_beta[t0 + tid], s);
    }
}

// ---------------- kernel E: softmax over beta[2048] -> alfa ----------------
__global__ void softmax_kernel() {
    __shared__ float sm[256];
    int tid = threadIdx.x;
    float v[8];
    float mx = -1e30f;
    #pragma unroll
    for (int i = 0; i < 8; i++) { v[i] = g_beta[tid * 8 + i]; mx = fmaxf(mx, v[i]); }
    sm[tid] = mx; __syncthreads();
    for (int s = 128; s; s >>= 1) { if (tid < s) sm[tid] = fmaxf(sm[tid], sm[tid + s]); __syncthreads(); }
    mx = sm[0]; __syncthreads();
    float sum = 0.0f;
    #pragma unroll
    for (int i = 0; i < 8; i++) { v[i] = __expf(v[i] - mx); sum += v[i]; }
    sm[tid] = sum; __syncthreads();
    for (int s = 128; s; s >>= 1) { if (tid < s) sm[tid] += sm[tid + s]; __syncthreads(); }
    float inv = 1.0f / sm[0];
    #pragma unroll
    for (int i = 0; i < 8; i++) g_alfa[tid * 8 + i] = v[i] * inv;
}

// ---------------- kernel F: s[j] = sum_t alfa[t] * prod[t,j] ----------------
__global__ void sred_kernel() {
    int tid = threadIdx.x;
    int t0 = blockIdx.x * 64;
    float4 acc = make_float4(0.f, 0.f, 0.f, 0.f);
    const float4* p4 = (const float4*)g_prod;
    for (int t = 0; t < 64; t++) {
        float a = g_alfa[t0 + t];
        float4 p = p4[(size_t)(t0 + t) * 256 + tid];
        acc.x += a * p.x; acc.y += a * p.y; acc.z += a * p.z; acc.w += a * p.w;
    }
    atomicAdd(&g_s[tid * 4 + 0], acc.x);
    atomicAdd(&g_s[tid * 4 + 1], acc.y);
    atomicAdd(&g_s[tid * 4 + 2], acc.z);
    atomicAdd(&g_s[tid * 4 + 3], acc.w);
}

// ---------------- kernel G: out[p] = s · lin2_w[p,:] + lin2_b[p], p=0..2 ----------------
__global__ void final_kernel(const float* __restrict__ l2w, const float* __restrict__ l2b,
                             float* __restrict__ out) {
    int wp = threadIdx.x >> 5, lane = threadIdx.x & 31;
    if (wp < 3) {
        float s = 0.0f;
        for (int j = lane; j < HDIM; j += 32)
            s += g_s[j] * l2w[wp * HDIM + j];
        #pragma unroll
        for (int off = 16; off; off >>= 1) s += __shfl_xor_sync(0xffffffffu, s, off);
        if (lane == 0) out[wp] = s + l2b[wp];
    }
}

// ---------------- launch ----------------
extern "C" void kernel_launch(void* const* d_in, const int* in_sizes, int n_in,
                              void* d_out, int out_size) {
    (void)in_sizes; (void)n_in; (void)out_size;
    const int*   x   = (const int*)d_in[0];
    const int*   ts  = (const int*)d_in[1];
    const int*   te  = (const int*)d_in[2];
    const float* emb = (const float*)d_in[3];
    const float* wil = (const float*)d_in[4];
    const float* whl = (const float*)d_in[5];
    const float* bil = (const float*)d_in[6];
    const float* bhl = (const float*)d_in[7];
    const float* wir = (const float*)d_in[8];
    const float* whr = (const float*)d_in[9];
    const float* bir = (const float*)d_in[10];
    const float* bhr = (const float*)d_in[11];
    const float* l1w = (const float*)d_in[12];
    const float* l1b = (const float*)d_in[13];
    const float* u   = (const float*)d_in[14];
    const float* l2w = (const float*)d_in[15];
    const float* l2b = (const float*)d_in[16];
    float* out = (float*)d_out;

    prep_kernel<<<8, 128>>>(x, ts, te, emb);
    zvec_kernel<<<8192, 128>>>(x, emb, wil, bil, bhl, wir, bir, bhr);
    lstm_kernel<<<GB, TB>>>(whl, whr);
    beta_kernel<<<dim3(LSEQ / 32, HDIM / 128), 256>>>(l1w, l1b, u);
    softmax_kernel<<<1, 256>>>();
    sred_kernel<<<32, 256>>>();
    final_kernel<<<1, 128>>>(l2w, l2b, out);
}